// round 1
// baseline (speedup 1.0000x reference)
#include <cuda_runtime.h>

// out[l, o] = (sum_{w=0..3} sum_i x[l-1+w, i] * K[w, i, o] + conv_b[o]) * D_param[o]
// == GEMM: A = x with per-chunk row offsets (zero padded), B = conv_kernel viewed (8192, 2048)

#define L_SEQ 2048
#define DDIM  2048
#define KTOT  8192

#define BM 128
#define BN 128
#define BK 16
#define TM 8
#define TN 8
// threads = (BM/TM) * (BN/TN) = 16 * 16 = 256

__global__ __launch_bounds__(256, 2) void mamba_conv_sgemm(
    const float* __restrict__ x,        // (2048, 2048)
    const float* __restrict__ wmat,     // (8192, 2048) = conv_kernel
    const float* __restrict__ conv_b,   // (2048,)
    const float* __restrict__ D_param,  // (2048,)
    float* __restrict__ out)            // (2048, 2048)
{
    __shared__ float As[BK][BM];   // A stored transposed: As[k][m]
    __shared__ float Bs[BK][BN];

    const int bm = blockIdx.y * BM;
    const int bn = blockIdx.x * BN;

    const int tid  = threadIdx.x;     // 0..255
    const int tcol = tid & 15;        // n direction
    const int trow = tid >> 4;        // m direction

    float acc[TM][TN];
    #pragma unroll
    for (int i = 0; i < TM; i++)
        #pragma unroll
        for (int j = 0; j < TN; j++)
            acc[i][j] = 0.0f;

    for (int kt = 0; kt < KTOT; kt += BK) {
        // 2048 % BK == 0, so the conv-tap index w is constant within a k-tile
        const int wsel  = kt >> 11;     // 0..3
        const int ibase = kt & 2047;

        // ---- load A tile (BM x BK) as float4, store transposed ----
        // 128 rows * 4 float4/row = 512 float4; 2 per thread
        #pragma unroll
        for (int f0 = 0; f0 < 2; f0++) {
            int f = tid + f0 * 256;
            int m = f >> 2;             // 0..127
            int c = (f & 3) * 4;        // 0,4,8,12
            int xr = bm + m + wsel - 1; // shifted row, may be OOB
            float4 v = make_float4(0.f, 0.f, 0.f, 0.f);
            if (xr >= 0 && xr < L_SEQ)
                v = *reinterpret_cast<const float4*>(x + (size_t)xr * DDIM + ibase + c);
            As[c + 0][m] = v.x;
            As[c + 1][m] = v.y;
            As[c + 2][m] = v.z;
            As[c + 3][m] = v.w;
        }

        // ---- load B tile (BK x BN) as float4 ----
        // 16 rows * 32 float4/row = 512 float4; 2 per thread
        #pragma unroll
        for (int f0 = 0; f0 < 2; f0++) {
            int f = tid + f0 * 256;
            int r = f >> 5;             // 0..15
            int c = (f & 31) * 4;       // 0..124
            float4 v = *reinterpret_cast<const float4*>(
                wmat + (size_t)(kt + r) * DDIM + bn + c);
            *reinterpret_cast<float4*>(&Bs[r][c]) = v;
        }

        __syncthreads();

        #pragma unroll
        for (int k = 0; k < BK; k++) {
            float af[TM], bf[TN];
            float4 a0 = *reinterpret_cast<const float4*>(&As[k][trow * TM]);
            float4 a1 = *reinterpret_cast<const float4*>(&As[k][trow * TM + 4]);
            float4 b0 = *reinterpret_cast<const float4*>(&Bs[k][tcol * TN]);
            float4 b1 = *reinterpret_cast<const float4*>(&Bs[k][tcol * TN + 4]);
            af[0] = a0.x; af[1] = a0.y; af[2] = a0.z; af[3] = a0.w;
            af[4] = a1.x; af[5] = a1.y; af[6] = a1.z; af[7] = a1.w;
            bf[0] = b0.x; bf[1] = b0.y; bf[2] = b0.z; bf[3] = b0.w;
            bf[4] = b1.x; bf[5] = b1.y; bf[6] = b1.z; bf[7] = b1.w;
            #pragma unroll
            for (int i = 0; i < TM; i++)
                #pragma unroll
                for (int j = 0; j < TN; j++)
                    acc[i][j] = fmaf(af[i], bf[j], acc[i][j]);
        }

        __syncthreads();
    }

    // ---- epilogue: (acc + conv_b[n]) * D_param[n] ----
    #pragma unroll
    for (int i = 0; i < TM; i++) {
        int row = bm + trow * TM + i;
        #pragma unroll
        for (int j = 0; j < TN; j += 4) {
            int col = bn + tcol * TN + j;
            float4 cb = *reinterpret_cast<const float4*>(conv_b + col);
            float4 dp = *reinterpret_cast<const float4*>(D_param + col);
            float4 o;
            o.x = (acc[i][j + 0] + cb.x) * dp.x;
            o.y = (acc[i][j + 1] + cb.y) * dp.y;
            o.z = (acc[i][j + 2] + cb.z) * dp.z;
            o.w = (acc[i][j + 3] + cb.w) * dp.w;
            *reinterpret_cast<float4*>(out + (size_t)row * DDIM + col) = o;
        }
    }
}

extern "C" void kernel_launch(void* const* d_in, const int* in_sizes, int n_in,
                              void* d_out, int out_size) {
    // metadata order: x, dt_W, dt_b, conv_kernel, conv_b, A_param, D_param
    const float* x       = (const float*)d_in[0];
    const float* conv_k  = (const float*)d_in[3];   // (4, 2048, 2048) == (8192, 2048)
    const float* conv_b  = (const float*)d_in[4];
    const float* D_param = (const float*)d_in[6];
    float* out = (float*)d_out;

    dim3 grid(DDIM / BN, L_SEQ / BM);   // (16, 16)
    mamba_conv_sgemm<<<grid, 256>>>(x, conv_k, conv_b, D_param, out);
}

// round 3
// speedup vs baseline: 2.1391x; 2.1391x over previous
#include <cuda_runtime.h>
#include <cuda_bf16.h>
#include <cstdint>

#define L_SEQ 2048
#define DDIM  2048
#define KTOT  8192
#define BM 128
#define BN 128
#define BK 32
#define NKT (KTOT / BK)        // 256 k-tiles
#define STAGES 3

// stage layout: Ah | Al | Bh | Bl, each 128 rows x 80B (64B data + 16B pad)
#define ROW_S 80
#define TILE_BYTES (128 * ROW_S)           // 10240
#define STAGE_BYTES (4 * TILE_BYTES)       // 40960
#define AH_OFF 0
#define AL_OFF TILE_BYTES
#define BH_OFF (2 * TILE_BYTES)
#define BL_OFF (3 * TILE_BYTES)
#define SMEM_TOTAL (STAGES * STAGE_BYTES)  // 122880

// ---------------- device scratch ----------------
__device__ __nv_bfloat16 g_x_hi[L_SEQ * DDIM];
__device__ __nv_bfloat16 g_x_lo[L_SEQ * DDIM];
__device__ __nv_bfloat16 g_wt_hi[DDIM * KTOT];   // WT[n][k] K-major
__device__ __nv_bfloat16 g_wt_lo[DDIM * KTOT];

// ---------------- helpers ----------------
__device__ __forceinline__ uint32_t smem_u32(const void* p) {
    uint32_t a;
    asm("{ .reg .u64 t; cvta.to.shared.u64 t, %1; cvt.u32.u64 %0, t; }" : "=r"(a) : "l"(p));
    return a;
}
__device__ __forceinline__ void cp_async_16(uint32_t dst, const void* src, int src_sz) {
    asm volatile("cp.async.cg.shared.global [%0], [%1], 16, %2;"
                 :: "r"(dst), "l"(src), "r"(src_sz));
}
#define CP_COMMIT() asm volatile("cp.async.commit_group;" ::: "memory")
#define CP_WAIT1()  asm volatile("cp.async.wait_group 1;" ::: "memory")
#define CP_WAIT0()  asm volatile("cp.async.wait_group 0;" ::: "memory")

__device__ __forceinline__ void ldm_x4(uint32_t* r, uint32_t addr) {
    asm volatile("ldmatrix.sync.aligned.m8n8.x4.shared.b16 {%0,%1,%2,%3}, [%4];"
                 : "=r"(r[0]), "=r"(r[1]), "=r"(r[2]), "=r"(r[3]) : "r"(addr));
}
__device__ __forceinline__ void mma16816(float* c, const uint32_t* a,
                                         uint32_t b0, uint32_t b1) {
    asm volatile(
        "mma.sync.aligned.m16n8k16.row.col.f32.bf16.bf16.f32 "
        "{%0,%1,%2,%3}, {%4,%5,%6,%7}, {%8,%9}, {%0,%1,%2,%3};"
        : "+f"(c[0]), "+f"(c[1]), "+f"(c[2]), "+f"(c[3])
        : "r"(a[0]), "r"(a[1]), "r"(a[2]), "r"(a[3]), "r"(b0), "r"(b1));
}

// ---------------- prep: split x into bf16 hi/lo ----------------
__global__ void split_x_kernel(const float* __restrict__ x) {
    int i = blockIdx.x * 256 + threadIdx.x;
    float4 v = reinterpret_cast<const float4*>(x)[i];
    __nv_bfloat16 h0 = __float2bfloat16(v.x), h1 = __float2bfloat16(v.y);
    __nv_bfloat16 h2 = __float2bfloat16(v.z), h3 = __float2bfloat16(v.w);
    __nv_bfloat16 l0 = __float2bfloat16(v.x - __bfloat162float(h0));
    __nv_bfloat16 l1 = __float2bfloat16(v.y - __bfloat162float(h1));
    __nv_bfloat16 l2 = __float2bfloat16(v.z - __bfloat162float(h2));
    __nv_bfloat16 l3 = __float2bfloat16(v.w - __bfloat162float(h3));
    __nv_bfloat162* hp = reinterpret_cast<__nv_bfloat162*>(g_x_hi);
    __nv_bfloat162* lp = reinterpret_cast<__nv_bfloat162*>(g_x_lo);
    hp[2 * i] = __nv_bfloat162(h0, h1); hp[2 * i + 1] = __nv_bfloat162(h2, h3);
    lp[2 * i] = __nv_bfloat162(l0, l1); lp[2 * i + 1] = __nv_bfloat162(l2, l3);
}

// ---------------- prep: split + transpose W -> WT[n][k] ----------------
__global__ void split_w_kernel(const float* __restrict__ w) {
    __shared__ float tile[32][33];
    int nt = blockIdx.x * 32;
    int kt = blockIdx.y * 32;
    int tx = threadIdx.x, ty = threadIdx.y;
    #pragma unroll
    for (int r = ty; r < 32; r += 8)
        tile[r][tx] = w[(size_t)(kt + r) * DDIM + nt + tx];
    __syncthreads();
    #pragma unroll
    for (int r = ty; r < 32; r += 8) {
        float v = tile[tx][r];                 // w[kt+tx][nt+r]
        __nv_bfloat16 h = __float2bfloat16(v);
        __nv_bfloat16 l = __float2bfloat16(v - __bfloat162float(h));
        size_t o = (size_t)(nt + r) * KTOT + kt + tx;
        g_wt_hi[o] = h;
        g_wt_lo[o] = l;
    }
}

// ---------------- GEMM tile loader ----------------
__device__ __forceinline__ void load_stage(uint32_t sbase, int stage, int kt,
                                           int bm, int bn, int tid) {
    const int w = kt >> 6;                    // conv tap (64 tiles of 32 per tap)
    const int ibase = (kt & 63) * BK;
    const int kcol = kt * BK;
    const uint32_t st = sbase + stage * STAGE_BYTES;
    // 4 tiles x 128 rows x 4 chunks = 2048 chunks of 16B; 8 per thread
    #pragma unroll
    for (int it = 0; it < 8; it++) {
        int i = tid + it * 256;
        int tile = i >> 9;                    // 0..3: Ah, Al, Bh, Bl
        int r = (i >> 2) & 127;
        int q = i & 3;
        uint32_t dst = st + tile * TILE_BYTES + r * ROW_S + q * 16;
        if (tile < 2) {
            int xr = bm + r + w - 1;
            int ok = (xr >= 0 && xr < L_SEQ) ? 16 : 0;
            int xc = xr < 0 ? 0 : (xr >= L_SEQ ? L_SEQ - 1 : xr);
            const __nv_bfloat16* src =
                (tile ? g_x_lo : g_x_hi) + (size_t)xc * DDIM + ibase + q * 8;
            cp_async_16(dst, src, ok);
        } else {
            const __nv_bfloat16* src =
                (tile == 3 ? g_wt_lo : g_wt_hi) + (size_t)(bn + r) * KTOT + kcol + q * 8;
            cp_async_16(dst, src, 16);
        }
    }
}

// ---------------- GEMM ----------------
__global__ __launch_bounds__(256, 1) void mamba_gemm_mma(
    const float* __restrict__ conv_b, const float* __restrict__ D_param,
    float* __restrict__ out)
{
    extern __shared__ __align__(128) char smem[];
    const uint32_t sbase = smem_u32(smem);
    const int tid  = threadIdx.x;
    const int lane = tid & 31;
    const int wid  = tid >> 5;
    const int wm   = wid & 3;                  // 4 warps along M (32 rows each)
    const int wn   = wid >> 2;                 // 2 warps along N (64 cols each)
    const int bm = blockIdx.y * BM;
    const int bn = blockIdx.x * BN;

    float acc[2][8][4];
    #pragma unroll
    for (int mi = 0; mi < 2; mi++)
        #pragma unroll
        for (int ni = 0; ni < 8; ni++)
            #pragma unroll
            for (int j = 0; j < 4; j++)
                acc[mi][ni][j] = 0.0f;

    // fragment smem addresses (stage-relative)
    const uint32_t a_row  = wm * 32 + (lane & 15);
    const uint32_t a_coff = (lane >> 4) * 16;
    const uint32_t b_row  = wn * 64 + (lane & 7) + ((lane >> 4) << 3);
    const uint32_t b_coff = ((lane >> 3) & 1) * 16;

    // prologue: stages 0,1
    load_stage(sbase, 0, 0, bm, bn, tid); CP_COMMIT();
    load_stage(sbase, 1, 1, bm, bn, tid); CP_COMMIT();

    for (int kt = 0; kt < NKT; kt++) {
        if (kt == NKT - 1) { CP_WAIT0(); } else { CP_WAIT1(); }
        __syncthreads();

        if (kt + 2 < NKT) {
            load_stage(sbase, (kt + 2) % STAGES, kt + 2, bm, bn, tid);
            CP_COMMIT();
        }

        const uint32_t st = sbase + (kt % STAGES) * STAGE_BYTES;
        #pragma unroll
        for (int ks = 0; ks < 2; ks++) {
            uint32_t ah[2][4], al[2][4];
            uint32_t bh[4][4], bl[4][4];
            #pragma unroll
            for (int mi = 0; mi < 2; mi++) {
                uint32_t ar = st + (a_row + mi * 16) * ROW_S + ks * 32 + a_coff;
                ldm_x4(ah[mi], ar + AH_OFF);
                ldm_x4(al[mi], ar + AL_OFF);
            }
            #pragma unroll
            for (int np = 0; np < 4; np++) {
                uint32_t br = st + (b_row + np * 16) * ROW_S + ks * 32 + b_coff;
                ldm_x4(bh[np], br + BH_OFF);
                ldm_x4(bl[np], br + BL_OFF);
            }
            #pragma unroll
            for (int mi = 0; mi < 2; mi++)
                #pragma unroll
                for (int ni = 0; ni < 8; ni++) {
                    uint32_t h0 = bh[ni >> 1][(ni & 1) * 2];
                    uint32_t h1 = bh[ni >> 1][(ni & 1) * 2 + 1];
                    uint32_t l0 = bl[ni >> 1][(ni & 1) * 2];
                    uint32_t l1 = bl[ni >> 1][(ni & 1) * 2 + 1];
                    mma16816(acc[mi][ni], ah[mi], h0, h1);
                    mma16816(acc[mi][ni], ah[mi], l0, l1);
                    mma16816(acc[mi][ni], al[mi], h0, h1);
                }
        }
        __syncthreads();
    }

    // epilogue: (acc + conv_b[n]) * D_param[n], float2 stores from regs
    #pragma unroll
    for (int ni = 0; ni < 8; ni++) {
        int c = bn + wn * 64 + ni * 8 + (lane & 3) * 2;
        float2 cb = *reinterpret_cast<const float2*>(conv_b + c);
        float2 dp = *reinterpret_cast<const float2*>(D_param + c);
        #pragma unroll
        for (int mi = 0; mi < 2; mi++) {
            int r0 = bm + wm * 32 + mi * 16 + (lane >> 2);
            float2 o0, o1;
            o0.x = (acc[mi][ni][0] + cb.x) * dp.x;
            o0.y = (acc[mi][ni][1] + cb.y) * dp.y;
            o1.x = (acc[mi][ni][2] + cb.x) * dp.x;
            o1.y = (acc[mi][ni][3] + cb.y) * dp.y;
            *reinterpret_cast<float2*>(out + (size_t)r0 * DDIM + c) = o0;
            *reinterpret_cast<float2*>(out + (size_t)(r0 + 8) * DDIM + c) = o1;
        }
    }
}

// ---------------- launch ----------------
extern "C" void kernel_launch(void* const* d_in, const int* in_sizes, int n_in,
                              void* d_out, int out_size) {
    const float* x       = (const float*)d_in[0];
    const float* conv_k  = (const float*)d_in[3];
    const float* conv_b  = (const float*)d_in[4];
    const float* D_param = (const float*)d_in[6];
    float* out = (float*)d_out;

    split_x_kernel<<<(L_SEQ * DDIM / 4) / 256, 256>>>(x);
    split_w_kernel<<<dim3(DDIM / 32, KTOT / 32), dim3(32, 8)>>>(conv_k);

    cudaFuncSetAttribute(mamba_gemm_mma, cudaFuncAttributeMaxDynamicSharedMemorySize, SMEM_TOTAL);
    mamba_gemm_mma<<<dim3(DDIM / BN, L_SEQ / BM), 256, SMEM_TOTAL>>>(conv_b, D_param, out);
}

// round 4
// speedup vs baseline: 2.9053x; 1.3582x over previous
#include <cuda_runtime.h>
#include <cuda_bf16.h>
#include <cstdint>

#define L_SEQ 2048
#define DDIM  2048
#define KTOT  8192
#define BM 128
#define BN 128
#define BK 64
#define NKT (KTOT / BK)        // 128 k-tiles
#define STAGES 3

// stage: Ah | Al | Bh | Bl, each 128 rows x 128B, XOR-swizzled (no pad)
#define TILE_BYTES (128 * 128)             // 16384
#define STAGE_BYTES (4 * TILE_BYTES)       // 65536
#define AH_OFF 0
#define AL_OFF TILE_BYTES
#define BH_OFF (2 * TILE_BYTES)
#define BL_OFF (3 * TILE_BYTES)
#define SMEM_TOTAL (STAGES * STAGE_BYTES)  // 196608

// ---------------- device scratch ----------------
__device__ __nv_bfloat16 g_x_hi[L_SEQ * DDIM];
__device__ __nv_bfloat16 g_x_lo[L_SEQ * DDIM];
__device__ __nv_bfloat16 g_wt_hi[DDIM * KTOT];   // WT[n][k] K-major
__device__ __nv_bfloat16 g_wt_lo[DDIM * KTOT];

// ---------------- helpers ----------------
__device__ __forceinline__ uint32_t smem_u32(const void* p) {
    uint32_t a;
    asm("{ .reg .u64 t; cvta.to.shared.u64 t, %1; cvt.u32.u64 %0, t; }" : "=r"(a) : "l"(p));
    return a;
}
__device__ __forceinline__ void cp_async_16(uint32_t dst, const void* src, int src_sz) {
    asm volatile("cp.async.cg.shared.global [%0], [%1], 16, %2;"
                 :: "r"(dst), "l"(src), "r"(src_sz));
}
#define CP_COMMIT() asm volatile("cp.async.commit_group;" ::: "memory")
#define CP_WAIT1()  asm volatile("cp.async.wait_group 1;" ::: "memory")
#define CP_WAIT0()  asm volatile("cp.async.wait_group 0;" ::: "memory")

__device__ __forceinline__ void ldm_x4(uint32_t* r, uint32_t addr) {
    asm volatile("ldmatrix.sync.aligned.m8n8.x4.shared.b16 {%0,%1,%2,%3}, [%4];"
                 : "=r"(r[0]), "=r"(r[1]), "=r"(r[2]), "=r"(r[3]) : "r"(addr));
}
__device__ __forceinline__ void mma16816(float* c, const uint32_t* a,
                                         uint32_t b0, uint32_t b1) {
    asm volatile(
        "mma.sync.aligned.m16n8k16.row.col.f32.bf16.bf16.f32 "
        "{%0,%1,%2,%3}, {%4,%5,%6,%7}, {%8,%9}, {%0,%1,%2,%3};"
        : "+f"(c[0]), "+f"(c[1]), "+f"(c[2]), "+f"(c[3])
        : "r"(a[0]), "r"(a[1]), "r"(a[2]), "r"(a[3]), "r"(b0), "r"(b1));
}

// ---------------- prep: split x into bf16 hi/lo ----------------
__global__ void split_x_kernel(const float* __restrict__ x) {
    int i = blockIdx.x * 256 + threadIdx.x;
    float4 v = reinterpret_cast<const float4*>(x)[i];
    __nv_bfloat16 h0 = __float2bfloat16(v.x), h1 = __float2bfloat16(v.y);
    __nv_bfloat16 h2 = __float2bfloat16(v.z), h3 = __float2bfloat16(v.w);
    __nv_bfloat16 l0 = __float2bfloat16(v.x - __bfloat162float(h0));
    __nv_bfloat16 l1 = __float2bfloat16(v.y - __bfloat162float(h1));
    __nv_bfloat16 l2 = __float2bfloat16(v.z - __bfloat162float(h2));
    __nv_bfloat16 l3 = __float2bfloat16(v.w - __bfloat162float(h3));
    __nv_bfloat162* hp = reinterpret_cast<__nv_bfloat162*>(g_x_hi);
    __nv_bfloat162* lp = reinterpret_cast<__nv_bfloat162*>(g_x_lo);
    hp[2 * i] = __nv_bfloat162(h0, h1); hp[2 * i + 1] = __nv_bfloat162(h2, h3);
    lp[2 * i] = __nv_bfloat162(l0, l1); lp[2 * i + 1] = __nv_bfloat162(l2, l3);
}

// ---------------- prep: split + transpose W -> WT[n][k] ----------------
__global__ void split_w_kernel(const float* __restrict__ w) {
    __shared__ float tile[32][33];
    int nt = blockIdx.x * 32;
    int kt = blockIdx.y * 32;
    int tx = threadIdx.x, ty = threadIdx.y;
    #pragma unroll
    for (int r = ty; r < 32; r += 8)
        tile[r][tx] = w[(size_t)(kt + r) * DDIM + nt + tx];
    __syncthreads();
    #pragma unroll
    for (int r = ty; r < 32; r += 8) {
        float v = tile[tx][r];                 // w[kt+tx][nt+r]
        __nv_bfloat16 h = __float2bfloat16(v);
        __nv_bfloat16 l = __float2bfloat16(v - __bfloat162float(h));
        size_t o = (size_t)(nt + r) * KTOT + kt + tx;
        g_wt_hi[o] = h;
        g_wt_lo[o] = l;
    }
}

// ---------------- GEMM tile loader (BK=64: 4096 x 16B chunks) ----------------
__device__ __forceinline__ void load_stage(uint32_t sbase, int stage, int kt,
                                           int bm, int bn, int tid) {
    const int w = kt >> 5;                    // conv tap (32 tiles of 64 per tap)
    const int ibase = (kt & 31) * BK;
    const int kcol = kt * BK;
    const uint32_t st = sbase + stage * STAGE_BYTES;
    #pragma unroll
    for (int it = 0; it < 16; it++) {
        int i = tid + it * 256;
        int tile = i >> 10;                   // 0..3: Ah, Al, Bh, Bl
        int idx = i & 1023;
        int r = idx >> 3;                     // 0..127
        int q = idx & 7;                      // 16B chunk in row
        uint32_t dst = st + tile * TILE_BYTES + r * 128 + ((q ^ (r & 7)) << 4);
        if (tile < 2) {
            int xr = bm + r + w - 1;
            int ok = (xr >= 0 && xr < L_SEQ) ? 16 : 0;
            int xc = xr < 0 ? 0 : (xr >= L_SEQ ? L_SEQ - 1 : xr);
            const __nv_bfloat16* src =
                (tile ? g_x_lo : g_x_hi) + (size_t)xc * DDIM + ibase + q * 8;
            cp_async_16(dst, src, ok);
        } else {
            const __nv_bfloat16* src =
                (tile == 3 ? g_wt_lo : g_wt_hi) + (size_t)(bn + r) * KTOT + kcol + q * 8;
            cp_async_16(dst, src, 16);
        }
    }
}

// ---------------- GEMM ----------------
__global__ __launch_bounds__(256, 1) void mamba_gemm_mma(
    const float* __restrict__ conv_b, const float* __restrict__ D_param,
    float* __restrict__ out)
{
    extern __shared__ __align__(128) char smem[];
    const uint32_t sbase = smem_u32(smem);
    const int tid  = threadIdx.x;
    const int lane = tid & 31;
    const int wid  = tid >> 5;
    const int wm   = wid & 3;                  // 4 warps along M (32 rows each)
    const int wn   = wid >> 2;                 // 2 warps along N (64 cols each)
    const int bm = blockIdx.y * BM;
    const int bn = blockIdx.x * BN;

    float acc[2][8][4];
    #pragma unroll
    for (int mi = 0; mi < 2; mi++)
        #pragma unroll
        for (int ni = 0; ni < 8; ni++)
            #pragma unroll
            for (int j = 0; j < 4; j++)
                acc[mi][ni][j] = 0.0f;

    // fragment rows / chunk components (stage-relative)
    const uint32_t a_row   = wm * 32 + (lane & 15);
    const uint32_t a_chunk = (lane >> 4);          // + ks*2
    const uint32_t b_row   = wn * 64 + (lane & 7) + ((lane >> 4) << 3);
    const uint32_t b_chunk = ((lane >> 3) & 1);    // + ks*2

    // prologue: stages 0,1
    load_stage(sbase, 0, 0, bm, bn, tid); CP_COMMIT();
    load_stage(sbase, 1, 1, bm, bn, tid); CP_COMMIT();

    for (int kt = 0; kt < NKT; kt++) {
        if (kt == NKT - 1) { CP_WAIT0(); } else { CP_WAIT1(); }
        __syncthreads();

        if (kt + 2 < NKT) {
            load_stage(sbase, (kt + 2) % STAGES, kt + 2, bm, bn, tid);
            CP_COMMIT();
        }

        const uint32_t st = sbase + (kt % STAGES) * STAGE_BYTES;
        #pragma unroll
        for (int ks = 0; ks < 4; ks++) {
            uint32_t ah[2][4], al[2][4];
            uint32_t bh[4][4], bl[4][4];
            #pragma unroll
            for (int mi = 0; mi < 2; mi++) {
                uint32_t row = a_row + mi * 16;
                uint32_t ar = st + row * 128 + (((ks * 2 + a_chunk) ^ (row & 7)) << 4);
                ldm_x4(ah[mi], ar + AH_OFF);
                ldm_x4(al[mi], ar + AL_OFF);
            }
            #pragma unroll
            for (int np = 0; np < 4; np++) {
                uint32_t row = b_row + np * 16;
                uint32_t br = st + row * 128 + (((ks * 2 + b_chunk) ^ (row & 7)) << 4);
                ldm_x4(bh[np], br + BH_OFF);
                ldm_x4(bl[np], br + BL_OFF);
            }
            #pragma unroll
            for (int mi = 0; mi < 2; mi++)
                #pragma unroll
                for (int ni = 0; ni < 8; ni++) {
                    uint32_t h0 = bh[ni >> 1][(ni & 1) * 2];
                    uint32_t h1 = bh[ni >> 1][(ni & 1) * 2 + 1];
                    uint32_t l0 = bl[ni >> 1][(ni & 1) * 2];
                    uint32_t l1 = bl[ni >> 1][(ni & 1) * 2 + 1];
                    mma16816(acc[mi][ni], ah[mi], h0, h1);
                    mma16816(acc[mi][ni], ah[mi], l0, l1);
                    mma16816(acc[mi][ni], al[mi], h0, h1);
                }
        }
        __syncthreads();
    }

    // epilogue: (acc + conv_b[n]) * D_param[n]
    #pragma unroll
    for (int ni = 0; ni < 8; ni++) {
        int c = bn + wn * 64 + ni * 8 + (lane & 3) * 2;
        float2 cb = *reinterpret_cast<const float2*>(conv_b + c);
        float2 dp = *reinterpret_cast<const float2*>(D_param + c);
        #pragma unroll
        for (int mi = 0; mi < 2; mi++) {
            int r0 = bm + wm * 32 + mi * 16 + (lane >> 2);
            float2 o0, o1;
            o0.x = (acc[mi][ni][0] + cb.x) * dp.x;
            o0.y = (acc[mi][ni][1] + cb.y) * dp.y;
            o1.x = (acc[mi][ni][2] + cb.x) * dp.x;
            o1.y = (acc[mi][ni][3] + cb.y) * dp.y;
            *reinterpret_cast<float2*>(out + (size_t)r0 * DDIM + c) = o0;
            *reinterpret_cast<float2*>(out + (size_t)(r0 + 8) * DDIM + c) = o1;
        }
    }
}

// ---------------- launch ----------------
extern "C" void kernel_launch(void* const* d_in, const int* in_sizes, int n_in,
                              void* d_out, int out_size) {
    const float* x       = (const float*)d_in[0];
    const float* conv_k  = (const float*)d_in[3];
    const float* conv_b  = (const float*)d_in[4];
    const float* D_param = (const float*)d_in[6];
    float* out = (float*)d_out;

    split_x_kernel<<<(L_SEQ * DDIM / 4) / 256, 256>>>(x);
    split_w_kernel<<<dim3(DDIM / 32, KTOT / 32), dim3(32, 8)>>>(conv_k);

    cudaFuncSetAttribute(mamba_gemm_mma, cudaFuncAttributeMaxDynamicSharedMemorySize, SMEM_TOTAL);
    mamba_gemm_mma<<<dim3(DDIM / BN, L_SEQ / BM), 256, SMEM_TOTAL>>>(conv_b, D_param, out);
}

// round 5
// speedup vs baseline: 3.9203x; 1.3493x over previous
#include <cuda_runtime.h>
#include <cuda_fp16.h>
#include <cstdint>

#define L_SEQ 2048
#define DDIM  2048
#define KTOT  8192
#define BM 128
#define BN 128
#define BK 64
#define NKT (KTOT / BK)        // 128 k-tiles
#define STAGES 4

// stage: Ah | Al | B, each 128 rows x 128B, XOR-swizzled
#define TILE_BYTES (128 * 128)             // 16384
#define STAGE_BYTES (3 * TILE_BYTES)       // 49152
#define AH_OFF 0
#define AL_OFF TILE_BYTES
#define B_OFF  (2 * TILE_BYTES)
#define SMEM_TOTAL (STAGES * STAGE_BYTES)  // 196608

// ---------------- device scratch ----------------
__device__ __half g_x_hi[L_SEQ * DDIM];
__device__ __half g_x_lo[L_SEQ * DDIM];
__device__ __half g_wt[DDIM * KTOT];   // WT[n][k] K-major, fp16

// ---------------- helpers ----------------
__device__ __forceinline__ uint32_t smem_u32(const void* p) {
    uint32_t a;
    asm("{ .reg .u64 t; cvta.to.shared.u64 t, %1; cvt.u32.u64 %0, t; }" : "=r"(a) : "l"(p));
    return a;
}
__device__ __forceinline__ void cp_async_16(uint32_t dst, const void* src, int src_sz) {
    asm volatile("cp.async.cg.shared.global [%0], [%1], 16, %2;"
                 :: "r"(dst), "l"(src), "r"(src_sz));
}
#define CP_COMMIT() asm volatile("cp.async.commit_group;" ::: "memory")
#define CP_WAIT2()  asm volatile("cp.async.wait_group 2;" ::: "memory")
#define CP_WAIT1()  asm volatile("cp.async.wait_group 1;" ::: "memory")
#define CP_WAIT0()  asm volatile("cp.async.wait_group 0;" ::: "memory")

__device__ __forceinline__ void ldm_x4(uint32_t* r, uint32_t addr) {
    asm volatile("ldmatrix.sync.aligned.m8n8.x4.shared.b16 {%0,%1,%2,%3}, [%4];"
                 : "=r"(r[0]), "=r"(r[1]), "=r"(r[2]), "=r"(r[3]) : "r"(addr));
}
__device__ __forceinline__ void mma16816(float* c, const uint32_t* a,
                                         uint32_t b0, uint32_t b1) {
    asm volatile(
        "mma.sync.aligned.m16n8k16.row.col.f32.f16.f16.f32 "
        "{%0,%1,%2,%3}, {%4,%5,%6,%7}, {%8,%9}, {%0,%1,%2,%3};"
        : "+f"(c[0]), "+f"(c[1]), "+f"(c[2]), "+f"(c[3])
        : "r"(a[0]), "r"(a[1]), "r"(a[2]), "r"(a[3]), "r"(b0), "r"(b1));
}

// ---------------- prep: split x into fp16 hi/lo ----------------
__global__ void split_x_kernel(const float* __restrict__ x) {
    int i = blockIdx.x * 256 + threadIdx.x;
    float4 v = reinterpret_cast<const float4*>(x)[i];
    __half h0 = __float2half(v.x), h1 = __float2half(v.y);
    __half h2 = __float2half(v.z), h3 = __float2half(v.w);
    __half l0 = __float2half(v.x - __half2float(h0));
    __half l1 = __float2half(v.y - __half2float(h1));
    __half l2 = __float2half(v.z - __half2float(h2));
    __half l3 = __float2half(v.w - __half2float(h3));
    __half2* hp = reinterpret_cast<__half2*>(g_x_hi);
    __half2* lp = reinterpret_cast<__half2*>(g_x_lo);
    hp[2 * i] = __halves2half2(h0, h1); hp[2 * i + 1] = __halves2half2(h2, h3);
    lp[2 * i] = __halves2half2(l0, l1); lp[2 * i + 1] = __halves2half2(l2, l3);
}

// ---------------- prep: convert + transpose W -> WT[n][k] fp16 ----------------
__global__ void split_w_kernel(const float* __restrict__ w) {
    __shared__ float tile[32][33];
    int nt = blockIdx.x * 32;
    int kt = blockIdx.y * 32;
    int tx = threadIdx.x, ty = threadIdx.y;
    #pragma unroll
    for (int r = ty; r < 32; r += 8)
        tile[r][tx] = w[(size_t)(kt + r) * DDIM + nt + tx];
    __syncthreads();
    #pragma unroll
    for (int r = ty; r < 32; r += 8) {
        float v = tile[tx][r];                 // w[kt+tx][nt+r]
        g_wt[(size_t)(nt + r) * KTOT + kt + tx] = __float2half(v);
    }
}

// ---------------- GEMM tile loader (3 tiles x 1024 chunks) ----------------
__device__ __forceinline__ void load_stage(uint32_t sbase, int stage, int kt,
                                           int bm, int bn, int tid) {
    const int w = kt >> 5;                    // conv tap (32 tiles of 64 per tap)
    const int ibase = (kt & 31) * BK;
    const int kcol = kt * BK;
    const uint32_t st = sbase + stage * STAGE_BYTES;
    #pragma unroll
    for (int it = 0; it < 12; it++) {
        int i = tid + it * 256;
        int tile = i >> 10;                   // 0,1,2: Ah, Al, B
        int idx = i & 1023;
        int r = idx >> 3;                     // 0..127
        int q = idx & 7;                      // 16B chunk in row
        uint32_t dst = st + tile * TILE_BYTES + r * 128 + ((q ^ (r & 7)) << 4);
        if (tile < 2) {
            int xr = bm + r + w - 1;
            int ok = (xr >= 0 && xr < L_SEQ) ? 16 : 0;
            int xc = xr < 0 ? 0 : (xr >= L_SEQ ? L_SEQ - 1 : xr);
            const __half* src =
                (tile ? g_x_lo : g_x_hi) + (size_t)xc * DDIM + ibase + q * 8;
            cp_async_16(dst, src, ok);
        } else {
            const __half* src = g_wt + (size_t)(bn + r) * KTOT + kcol + q * 8;
            cp_async_16(dst, src, 16);
        }
    }
}

// ---------------- GEMM ----------------
__global__ __launch_bounds__(256, 1) void mamba_gemm_mma(
    const float* __restrict__ conv_b, const float* __restrict__ D_param,
    float* __restrict__ out)
{
    extern __shared__ __align__(128) char smem[];
    const uint32_t sbase = smem_u32(smem);
    const int tid  = threadIdx.x;
    const int lane = tid & 31;
    const int wid  = tid >> 5;
    const int wm   = wid & 3;                  // 4 warps along M (32 rows each)
    const int wn   = wid >> 2;                 // 2 warps along N (64 cols each)
    const int bm = blockIdx.y * BM;
    const int bn = blockIdx.x * BN;

    float acc[2][8][4];
    #pragma unroll
    for (int mi = 0; mi < 2; mi++)
        #pragma unroll
        for (int ni = 0; ni < 8; ni++)
            #pragma unroll
            for (int j = 0; j < 4; j++)
                acc[mi][ni][j] = 0.0f;

    const uint32_t a_row   = wm * 32 + (lane & 15);
    const uint32_t a_chunk = (lane >> 4);          // + ks*2
    const uint32_t b_row   = wn * 64 + (lane & 7) + ((lane >> 4) << 3);
    const uint32_t b_chunk = ((lane >> 3) & 1);    // + ks*2

    // prologue: stages 0..2
    load_stage(sbase, 0, 0, bm, bn, tid); CP_COMMIT();
    load_stage(sbase, 1, 1, bm, bn, tid); CP_COMMIT();
    load_stage(sbase, 2, 2, bm, bn, tid); CP_COMMIT();

    for (int kt = 0; kt < NKT; kt++) {
        // stage kt must be complete
        if (kt < NKT - 2)      { CP_WAIT2(); }
        else if (kt == NKT - 2){ CP_WAIT1(); }
        else                   { CP_WAIT0(); }
        __syncthreads();

        if (kt + 3 < NKT) {
            load_stage(sbase, (kt + 3) % STAGES, kt + 3, bm, bn, tid);
            CP_COMMIT();
        }

        const uint32_t st = sbase + (kt % STAGES) * STAGE_BYTES;
        #pragma unroll
        for (int ks = 0; ks < 4; ks++) {
            uint32_t ah[2][4], al[2][4];
            uint32_t bb[4][4];
            #pragma unroll
            for (int mi = 0; mi < 2; mi++) {
                uint32_t row = a_row + mi * 16;
                uint32_t ar = st + row * 128 + (((ks * 2 + a_chunk) ^ (row & 7)) << 4);
                ldm_x4(ah[mi], ar + AH_OFF);
                ldm_x4(al[mi], ar + AL_OFF);
            }
            #pragma unroll
            for (int np = 0; np < 4; np++) {
                uint32_t row = b_row + np * 16;
                uint32_t br = st + row * 128 + (((ks * 2 + b_chunk) ^ (row & 7)) << 4);
                ldm_x4(bb[np], br + B_OFF);
            }
            #pragma unroll
            for (int mi = 0; mi < 2; mi++)
                #pragma unroll
                for (int ni = 0; ni < 8; ni++) {
                    uint32_t b0 = bb[ni >> 1][(ni & 1) * 2];
                    uint32_t b1 = bb[ni >> 1][(ni & 1) * 2 + 1];
                    mma16816(acc[mi][ni], ah[mi], b0, b1);
                    mma16816(acc[mi][ni], al[mi], b0, b1);
                }
        }
        __syncthreads();
    }

    // epilogue: (acc + conv_b[n]) * D_param[n]
    #pragma unroll
    for (int ni = 0; ni < 8; ni++) {
        int c = bn + wn * 64 + ni * 8 + (lane & 3) * 2;
        float2 cb = *reinterpret_cast<const float2*>(conv_b + c);
        float2 dp = *reinterpret_cast<const float2*>(D_param + c);
        #pragma unroll
        for (int mi = 0; mi < 2; mi++) {
            int r0 = bm + wm * 32 + mi * 16 + (lane >> 2);
            float2 o0, o1;
            o0.x = (acc[mi][ni][0] + cb.x) * dp.x;
            o0.y = (acc[mi][ni][1] + cb.y) * dp.y;
            o1.x = (acc[mi][ni][2] + cb.x) * dp.x;
            o1.y = (acc[mi][ni][3] + cb.y) * dp.y;
            *reinterpret_cast<float2*>(out + (size_t)r0 * DDIM + c) = o0;
            *reinterpret_cast<float2*>(out + (size_t)(r0 + 8) * DDIM + c) = o1;
        }
    }
}

// ---------------- launch ----------------
extern "C" void kernel_launch(void* const* d_in, const int* in_sizes, int n_in,
                              void* d_out, int out_size) {
    const float* x       = (const float*)d_in[0];
    const float* conv_k  = (const float*)d_in[3];
    const float* conv_b  = (const float*)d_in[4];
    const float* D_param = (const float*)d_in[6];
    float* out = (float*)d_out;

    split_x_kernel<<<(L_SEQ * DDIM / 4) / 256, 256>>>(x);
    split_w_kernel<<<dim3(DDIM / 32, KTOT / 32), dim3(32, 8)>>>(conv_k);

    cudaFuncSetAttribute(mamba_gemm_mma, cudaFuncAttributeMaxDynamicSharedMemorySize, SMEM_TOTAL);
    mamba_gemm_mma<<<dim3(DDIM / BN, L_SEQ / BM), 256, SMEM_TOTAL>>>(conv_b, D_param, out);
}

// round 6
// speedup vs baseline: 6.0488x; 1.5430x over previous
#include <cuda_runtime.h>
#include <cuda_fp16.h>
#include <cstdint>

#define L_SEQ 2048
#define DDIM  2048
#define KTOT  8192
#define BM 128
#define BN 128
#define BK 64
#define NKT (KTOT / BK)        // 128 k-tiles
#define STAGES 5

// stage: A | B, each 128 rows x 128B, XOR-swizzled
#define TILE_BYTES (128 * 128)             // 16384
#define STAGE_BYTES (2 * TILE_BYTES)       // 32768
#define A_OFF 0
#define B_OFF TILE_BYTES
#define SMEM_TOTAL (STAGES * STAGE_BYTES)  // 163840

// ---------------- device scratch ----------------
__device__ __half g_x[L_SEQ * DDIM];
__device__ __half g_wt[DDIM * KTOT];   // WT[n][k] K-major, fp16

// ---------------- helpers ----------------
__device__ __forceinline__ uint32_t smem_u32(const void* p) {
    uint32_t a;
    asm("{ .reg .u64 t; cvta.to.shared.u64 t, %1; cvt.u32.u64 %0, t; }" : "=r"(a) : "l"(p));
    return a;
}
__device__ __forceinline__ void cp_async_16(uint32_t dst, const void* src, int src_sz) {
    asm volatile("cp.async.cg.shared.global [%0], [%1], 16, %2;"
                 :: "r"(dst), "l"(src), "r"(src_sz));
}
#define CP_COMMIT() asm volatile("cp.async.commit_group;" ::: "memory")
#define CP_WAIT3()  asm volatile("cp.async.wait_group 3;" ::: "memory")
#define CP_WAIT2()  asm volatile("cp.async.wait_group 2;" ::: "memory")
#define CP_WAIT1()  asm volatile("cp.async.wait_group 1;" ::: "memory")
#define CP_WAIT0()  asm volatile("cp.async.wait_group 0;" ::: "memory")

__device__ __forceinline__ void ldm_x4(uint32_t* r, uint32_t addr) {
    asm volatile("ldmatrix.sync.aligned.m8n8.x4.shared.b16 {%0,%1,%2,%3}, [%4];"
                 : "=r"(r[0]), "=r"(r[1]), "=r"(r[2]), "=r"(r[3]) : "r"(addr));
}
__device__ __forceinline__ void mma16816(float* c, const uint32_t* a,
                                         uint32_t b0, uint32_t b1) {
    asm volatile(
        "mma.sync.aligned.m16n8k16.row.col.f32.f16.f16.f32 "
        "{%0,%1,%2,%3}, {%4,%5,%6,%7}, {%8,%9}, {%0,%1,%2,%3};"
        : "+f"(c[0]), "+f"(c[1]), "+f"(c[2]), "+f"(c[3])
        : "r"(a[0]), "r"(a[1]), "r"(a[2]), "r"(a[3]), "r"(b0), "r"(b1));
}

// ---------------- prep: convert x -> fp16 ----------------
__global__ void split_x_kernel(const float* __restrict__ x) {
    int i = blockIdx.x * 256 + threadIdx.x;
    float4 v = reinterpret_cast<const float4*>(x)[i];
    __half2* hp = reinterpret_cast<__half2*>(g_x);
    hp[2 * i]     = __halves2half2(__float2half(v.x), __float2half(v.y));
    hp[2 * i + 1] = __halves2half2(__float2half(v.z), __float2half(v.w));
}

// ---------------- prep: convert + transpose W -> WT[n][k] fp16 ----------------
__global__ void split_w_kernel(const float* __restrict__ w) {
    __shared__ float tile[32][33];
    int nt = blockIdx.x * 32;
    int kt = blockIdx.y * 32;
    int tx = threadIdx.x, ty = threadIdx.y;
    #pragma unroll
    for (int r = ty; r < 32; r += 8)
        tile[r][tx] = w[(size_t)(kt + r) * DDIM + nt + tx];
    __syncthreads();
    #pragma unroll
    for (int r = ty; r < 32; r += 8) {
        float v = tile[tx][r];                 // w[kt+tx][nt+r]
        g_wt[(size_t)(nt + r) * KTOT + kt + tx] = __float2half(v);
    }
}

// ---------------- GEMM tile loader (2 tiles x 1024 chunks) ----------------
__device__ __forceinline__ void load_stage(uint32_t sbase, int stage, int kt,
                                           int bm, int bn, int tid) {
    const int w = kt >> 5;                    // conv tap (32 tiles of 64 per tap)
    const int ibase = (kt & 31) * BK;
    const int kcol = kt * BK;
    const uint32_t st = sbase + stage * STAGE_BYTES;
    #pragma unroll
    for (int it = 0; it < 8; it++) {
        int i = tid + it * 256;
        int tile = i >> 10;                   // 0: A, 1: B
        int idx = i & 1023;
        int r = idx >> 3;                     // 0..127
        int q = idx & 7;                      // 16B chunk in row
        uint32_t dst = st + tile * TILE_BYTES + r * 128 + ((q ^ (r & 7)) << 4);
        if (tile == 0) {
            int xr = bm + r + w - 1;
            int ok = (xr >= 0 && xr < L_SEQ) ? 16 : 0;
            int xc = xr < 0 ? 0 : (xr >= L_SEQ ? L_SEQ - 1 : xr);
            const __half* src = g_x + (size_t)xc * DDIM + ibase + q * 8;
            cp_async_16(dst, src, ok);
        } else {
            const __half* src = g_wt + (size_t)(bn + r) * KTOT + kcol + q * 8;
            cp_async_16(dst, src, 16);
        }
    }
}

// ---------------- GEMM ----------------
__global__ __launch_bounds__(256, 1) void mamba_gemm_mma(
    const float* __restrict__ conv_b, const float* __restrict__ D_param,
    float* __restrict__ out)
{
    extern __shared__ __align__(128) char smem[];
    const uint32_t sbase = smem_u32(smem);
    const int tid  = threadIdx.x;
    const int lane = tid & 31;
    const int wid  = tid >> 5;
    const int wm   = wid & 3;                  // 4 warps along M (32 rows each)
    const int wn   = wid >> 2;                 // 2 warps along N (64 cols each)
    const int bm = blockIdx.y * BM;
    const int bn = blockIdx.x * BN;

    float acc[2][8][4];
    #pragma unroll
    for (int mi = 0; mi < 2; mi++)
        #pragma unroll
        for (int ni = 0; ni < 8; ni++)
            #pragma unroll
            for (int j = 0; j < 4; j++)
                acc[mi][ni][j] = 0.0f;

    const uint32_t a_row   = wm * 32 + (lane & 15);
    const uint32_t a_chunk = (lane >> 4);          // + ks*2
    const uint32_t b_row   = wn * 64 + (lane & 7) + ((lane >> 4) << 3);
    const uint32_t b_chunk = ((lane >> 3) & 1);    // + ks*2

    // prologue: stages 0..3
    load_stage(sbase, 0, 0, bm, bn, tid); CP_COMMIT();
    load_stage(sbase, 1, 1, bm, bn, tid); CP_COMMIT();
    load_stage(sbase, 2, 2, bm, bn, tid); CP_COMMIT();
    load_stage(sbase, 3, 3, bm, bn, tid); CP_COMMIT();

    for (int kt = 0; kt < NKT; kt++) {
        // stage kt must be complete
        if (kt < NKT - 3)      { CP_WAIT3(); }
        else if (kt == NKT - 3){ CP_WAIT2(); }
        else if (kt == NKT - 2){ CP_WAIT1(); }
        else                   { CP_WAIT0(); }
        __syncthreads();

        if (kt + 4 < NKT) {
            load_stage(sbase, (kt + 4) % STAGES, kt + 4, bm, bn, tid);
            CP_COMMIT();
        }

        const uint32_t st = sbase + (kt % STAGES) * STAGE_BYTES;
        #pragma unroll
        for (int ks = 0; ks < 4; ks++) {
            uint32_t aa[2][4];
            uint32_t bb[4][4];
            #pragma unroll
            for (int mi = 0; mi < 2; mi++) {
                uint32_t row = a_row + mi * 16;
                uint32_t ar = st + row * 128 + (((ks * 2 + a_chunk) ^ (row & 7)) << 4);
                ldm_x4(aa[mi], ar + A_OFF);
            }
            #pragma unroll
            for (int np = 0; np < 4; np++) {
                uint32_t row = b_row + np * 16;
                uint32_t br = st + row * 128 + (((ks * 2 + b_chunk) ^ (row & 7)) << 4);
                ldm_x4(bb[np], br + B_OFF);
            }
            #pragma unroll
            for (int mi = 0; mi < 2; mi++)
                #pragma unroll
                for (int ni = 0; ni < 8; ni++) {
                    uint32_t b0 = bb[ni >> 1][(ni & 1) * 2];
                    uint32_t b1 = bb[ni >> 1][(ni & 1) * 2 + 1];
                    mma16816(acc[mi][ni], aa[mi], b0, b1);
                }
        }
        __syncthreads();
    }

    // epilogue: (acc + conv_b[n]) * D_param[n]
    #pragma unroll
    for (int ni = 0; ni < 8; ni++) {
        int c = bn + wn * 64 + ni * 8 + (lane & 3) * 2;
        float2 cb = *reinterpret_cast<const float2*>(conv_b + c);
        float2 dp = *reinterpret_cast<const float2*>(D_param + c);
        #pragma unroll
        for (int mi = 0; mi < 2; mi++) {
            int r0 = bm + wm * 32 + mi * 16 + (lane >> 2);
            float2 o0, o1;
            o0.x = (acc[mi][ni][0] + cb.x) * dp.x;
            o0.y = (acc[mi][ni][1] + cb.y) * dp.y;
            o1.x = (acc[mi][ni][2] + cb.x) * dp.x;
            o1.y = (acc[mi][ni][3] + cb.y) * dp.y;
            *reinterpret_cast<float2*>(out + (size_t)r0 * DDIM + c) = o0;
            *reinterpret_cast<float2*>(out + (size_t)(r0 + 8) * DDIM + c) = o1;
        }
    }
}

// ---------------- launch ----------------
extern "C" void kernel_launch(void* const* d_in, const int* in_sizes, int n_in,
                              void* d_out, int out_size) {
    const float* x       = (const float*)d_in[0];
    const float* conv_k  = (const float*)d_in[3];
    const float* conv_b  = (const float*)d_in[4];
    const float* D_param = (const float*)d_in[6];
    float* out = (float*)d_out;

    split_x_kernel<<<(L_SEQ * DDIM / 4) / 256, 256>>>(x);
    split_w_kernel<<<dim3(DDIM / 32, KTOT / 32), dim3(32, 8)>>>(conv_k);

    cudaFuncSetAttribute(mamba_gemm_mma, cudaFuncAttributeMaxDynamicSharedMemorySize, SMEM_TOTAL);
    mamba_gemm_mma<<<dim3(DDIM / BN, L_SEQ / BM), 256, SMEM_TOTAL>>>(conv_b, D_param, out);
}

// round 7
// speedup vs baseline: 7.3091x; 1.2083x over previous
#include <cuda_runtime.h>
#include <cuda_fp16.h>
#include <cstdint>

#define L_SEQ 2048
#define DDIM  2048
#define KTOT  8192
#define BM 128
#define BN 128
#define BK 64
#define NKT (KTOT / BK)        // 128 k-tiles
#define STAGES 3

// stage: A | B, each 128 rows x 128B, XOR-swizzled
#define TILE_BYTES (128 * 128)             // 16384
#define STAGE_BYTES (2 * TILE_BYTES)       // 32768
#define A_OFF 0
#define B_OFF TILE_BYTES
#define SMEM_TOTAL (STAGES * STAGE_BYTES)  // 98304 -> 2 CTAs/SM

// ---------------- device scratch ----------------
__device__ __half g_x[L_SEQ * DDIM];
__device__ __half g_wt[DDIM * KTOT];   // WT[n][k] K-major, fp16

// ---------------- helpers ----------------
__device__ __forceinline__ uint32_t smem_u32(const void* p) {
    uint32_t a;
    asm("{ .reg .u64 t; cvta.to.shared.u64 t, %1; cvt.u32.u64 %0, t; }" : "=r"(a) : "l"(p));
    return a;
}
__device__ __forceinline__ void cp_async_16(uint32_t dst, const void* src, int src_sz) {
    asm volatile("cp.async.cg.shared.global [%0], [%1], 16, %2;"
                 :: "r"(dst), "l"(src), "r"(src_sz));
}
#define CP_COMMIT() asm volatile("cp.async.commit_group;" ::: "memory")
#define CP_WAIT1()  asm volatile("cp.async.wait_group 1;" ::: "memory")
#define CP_WAIT0()  asm volatile("cp.async.wait_group 0;" ::: "memory")

__device__ __forceinline__ void ldm_x4(uint32_t* r, uint32_t addr) {
    asm volatile("ldmatrix.sync.aligned.m8n8.x4.shared.b16 {%0,%1,%2,%3}, [%4];"
                 : "=r"(r[0]), "=r"(r[1]), "=r"(r[2]), "=r"(r[3]) : "r"(addr));
}
__device__ __forceinline__ void mma16816(float* c, const uint32_t* a,
                                         uint32_t b0, uint32_t b1) {
    asm volatile(
        "mma.sync.aligned.m16n8k16.row.col.f32.f16.f16.f32 "
        "{%0,%1,%2,%3}, {%4,%5,%6,%7}, {%8,%9}, {%0,%1,%2,%3};"
        : "+f"(c[0]), "+f"(c[1]), "+f"(c[2]), "+f"(c[3])
        : "r"(a[0]), "r"(a[1]), "r"(a[2]), "r"(a[3]), "r"(b0), "r"(b1));
}

// ---------------- prep: convert x -> fp16 ----------------
__global__ void split_x_kernel(const float* __restrict__ x) {
    int i = blockIdx.x * 256 + threadIdx.x;
    float4 v = reinterpret_cast<const float4*>(x)[i];
    __half2* hp = reinterpret_cast<__half2*>(g_x);
    hp[2 * i]     = __halves2half2(__float2half(v.x), __float2half(v.y));
    hp[2 * i + 1] = __halves2half2(__float2half(v.z), __float2half(v.w));
}

// ---------------- prep: convert + transpose W -> WT[n][k] fp16 ----------------
__global__ void split_w_kernel(const float* __restrict__ w) {
    __shared__ float tile[32][33];
    int nt = blockIdx.x * 32;
    int kt = blockIdx.y * 32;
    int tx = threadIdx.x, ty = threadIdx.y;
    #pragma unroll
    for (int r = ty; r < 32; r += 8)
        tile[r][tx] = w[(size_t)(kt + r) * DDIM + nt + tx];
    __syncthreads();
    #pragma unroll
    for (int r = ty; r < 32; r += 8) {
        float v = tile[tx][r];                 // w[kt+tx][nt+r]
        g_wt[(size_t)(nt + r) * KTOT + kt + tx] = __float2half(v);
    }
}

// ---------------- GEMM tile loader (2 tiles x 1024 chunks) ----------------
__device__ __forceinline__ void load_stage(uint32_t sbase, int stage, int kt,
                                           int bm, int bn, int tid) {
    const int w = kt >> 5;                    // conv tap (32 tiles of 64 per tap)
    const int ibase = (kt & 31) * BK;
    const int kcol = kt * BK;
    const uint32_t st = sbase + stage * STAGE_BYTES;
    #pragma unroll
    for (int it = 0; it < 8; it++) {
        int i = tid + it * 256;
        int tile = i >> 10;                   // 0: A, 1: B
        int idx = i & 1023;
        int r = idx >> 3;                     // 0..127
        int q = idx & 7;                      // 16B chunk in row
        uint32_t dst = st + tile * TILE_BYTES + r * 128 + ((q ^ (r & 7)) << 4);
        if (tile == 0) {
            int xr = bm + r + w - 1;
            int ok = (xr >= 0 && xr < L_SEQ) ? 16 : 0;
            int xc = xr < 0 ? 0 : (xr >= L_SEQ ? L_SEQ - 1 : xr);
            const __half* src = g_x + (size_t)xc * DDIM + ibase + q * 8;
            cp_async_16(dst, src, ok);
        } else {
            const __half* src = g_wt + (size_t)(bn + r) * KTOT + kcol + q * 8;
            cp_async_16(dst, src, 16);
        }
    }
}

// ---------------- GEMM ----------------
__global__ __launch_bounds__(256, 2) void mamba_gemm_mma(
    const float* __restrict__ conv_b, const float* __restrict__ D_param,
    float* __restrict__ out)
{
    extern __shared__ __align__(128) char smem[];
    const uint32_t sbase = smem_u32(smem);
    const int tid  = threadIdx.x;
    const int lane = tid & 31;
    const int wid  = tid >> 5;
    const int wm   = wid & 3;                  // 4 warps along M (32 rows each)
    const int wn   = wid >> 2;                 // 2 warps along N (64 cols each)
    const int bm = blockIdx.y * BM;
    const int bn = blockIdx.x * BN;

    float acc[2][8][4];
    #pragma unroll
    for (int mi = 0; mi < 2; mi++)
        #pragma unroll
        for (int ni = 0; ni < 8; ni++)
            #pragma unroll
            for (int j = 0; j < 4; j++)
                acc[mi][ni][j] = 0.0f;

    const uint32_t a_row   = wm * 32 + (lane & 15);
    const uint32_t a_chunk = (lane >> 4);          // + ks*2
    const uint32_t b_row   = wn * 64 + (lane & 7) + ((lane >> 4) << 3);
    const uint32_t b_chunk = ((lane >> 3) & 1);    // + ks*2

    // prologue: stages 0,1
    load_stage(sbase, 0, 0, bm, bn, tid); CP_COMMIT();
    load_stage(sbase, 1, 1, bm, bn, tid); CP_COMMIT();

    for (int kt = 0; kt < NKT; kt++) {
        // stage kt must be complete
        if (kt < NKT - 1) { CP_WAIT1(); } else { CP_WAIT0(); }
        __syncthreads();

        if (kt + 2 < NKT) {
            load_stage(sbase, (kt + 2) % STAGES, kt + 2, bm, bn, tid);
            CP_COMMIT();
        }

        const uint32_t st = sbase + (kt % STAGES) * STAGE_BYTES;
        #pragma unroll
        for (int ks = 0; ks < 4; ks++) {
            uint32_t aa[2][4];
            uint32_t bb[4][4];
            #pragma unroll
            for (int mi = 0; mi < 2; mi++) {
                uint32_t row = a_row + mi * 16;
                uint32_t ar = st + row * 128 + (((ks * 2 + a_chunk) ^ (row & 7)) << 4);
                ldm_x4(aa[mi], ar + A_OFF);
            }
            #pragma unroll
            for (int np = 0; np < 4; np++) {
                uint32_t row = b_row + np * 16;
                uint32_t br = st + row * 128 + (((ks * 2 + b_chunk) ^ (row & 7)) << 4);
                ldm_x4(bb[np], br + B_OFF);
            }
            #pragma unroll
            for (int mi = 0; mi < 2; mi++)
                #pragma unroll
                for (int ni = 0; ni < 8; ni++) {
                    uint32_t b0 = bb[ni >> 1][(ni & 1) * 2];
                    uint32_t b1 = bb[ni >> 1][(ni & 1) * 2 + 1];
                    mma16816(acc[mi][ni], aa[mi], b0, b1);
                }
        }
        __syncthreads();
    }

    // epilogue: (acc + conv_b[n]) * D_param[n]
    #pragma unroll
    for (int ni = 0; ni < 8; ni++) {
        int c = bn + wn * 64 + ni * 8 + (lane & 3) * 2;
        float2 cb = *reinterpret_cast<const float2*>(conv_b + c);
        float2 dp = *reinterpret_cast<const float2*>(D_param + c);
        #pragma unroll
        for (int mi = 0; mi < 2; mi++) {
            int r0 = bm + wm * 32 + mi * 16 + (lane >> 2);
            float2 o0, o1;
            o0.x = (acc[mi][ni][0] + cb.x) * dp.x;
            o0.y = (acc[mi][ni][1] + cb.y) * dp.y;
            o1.x = (acc[mi][ni][2] + cb.x) * dp.x;
            o1.y = (acc[mi][ni][3] + cb.y) * dp.y;
            *reinterpret_cast<float2*>(out + (size_t)r0 * DDIM + c) = o0;
            *reinterpret_cast<float2*>(out + (size_t)(r0 + 8) * DDIM + c) = o1;
        }
    }
}

// ---------------- launch ----------------
extern "C" void kernel_launch(void* const* d_in, const int* in_sizes, int n_in,
                              void* d_out, int out_size) {
    const float* x       = (const float*)d_in[0];
    const float* conv_k  = (const float*)d_in[3];
    const float* conv_b  = (const float*)d_in[4];
    const float* D_param = (const float*)d_in[6];
    float* out = (float*)d_out;

    split_x_kernel<<<(L_SEQ * DDIM / 4) / 256, 256>>>(x);
    split_w_kernel<<<dim3(DDIM / 32, KTOT / 32), dim3(32, 8)>>>(conv_k);

    cudaFuncSetAttribute(mamba_gemm_mma, cudaFuncAttributeMaxDynamicSharedMemorySize, SMEM_TOTAL);
    mamba_gemm_mma<<<dim3(DDIM / BN, L_SEQ / BM), 256, SMEM_TOTAL>>>(conv_b, D_param, out);
}

// round 8
// speedup vs baseline: 7.7247x; 1.0569x over previous
#include <cuda_runtime.h>
#include <cuda_fp16.h>
#include <cstdint>

#define L_SEQ 2048
#define DDIM  2048
#define KTOT  8192
#define BM 128
#define BN 128
#define BK 64
#define NKT (KTOT / BK)        // 128 k-tiles
#define STAGES 3

// stage: A | B, each 128 rows x 128B, XOR-swizzled
#define TILE_BYTES (128 * 128)             // 16384
#define STAGE_BYTES (2 * TILE_BYTES)       // 32768
#define A_OFF 0
#define B_OFF TILE_BYTES
#define SMEM_TOTAL (STAGES * STAGE_BYTES)  // 98304 -> 2 CTAs/SM

// ---------------- device scratch ----------------
__device__ __half g_x[L_SEQ * DDIM];
__device__ __half g_wt[DDIM * KTOT];   // WT[n][k] K-major, fp16

// ---------------- helpers ----------------
__device__ __forceinline__ uint32_t smem_u32(const void* p) {
    uint32_t a;
    asm("{ .reg .u64 t; cvta.to.shared.u64 t, %1; cvt.u32.u64 %0, t; }" : "=r"(a) : "l"(p));
    return a;
}
__device__ __forceinline__ void cp_async_16(uint32_t dst, const void* src, int src_sz) {
    asm volatile("cp.async.cg.shared.global [%0], [%1], 16, %2;"
                 :: "r"(dst), "l"(src), "r"(src_sz));
}
#define CP_COMMIT() asm volatile("cp.async.commit_group;" ::: "memory")
#define CP_WAIT1()  asm volatile("cp.async.wait_group 1;" ::: "memory")
#define CP_WAIT0()  asm volatile("cp.async.wait_group 0;" ::: "memory")

__device__ __forceinline__ void ldm_x4(uint32_t* r, uint32_t addr) {
    asm volatile("ldmatrix.sync.aligned.m8n8.x4.shared.b16 {%0,%1,%2,%3}, [%4];"
                 : "=r"(r[0]), "=r"(r[1]), "=r"(r[2]), "=r"(r[3]) : "r"(addr));
}
__device__ __forceinline__ void mma16816(float* c, const uint32_t* a,
                                         uint32_t b0, uint32_t b1) {
    asm volatile(
        "mma.sync.aligned.m16n8k16.row.col.f32.f16.f16.f32 "
        "{%0,%1,%2,%3}, {%4,%5,%6,%7}, {%8,%9}, {%0,%1,%2,%3};"
        : "+f"(c[0]), "+f"(c[1]), "+f"(c[2]), "+f"(c[3])
        : "r"(a[0]), "r"(a[1]), "r"(a[2]), "r"(a[3]), "r"(b0), "r"(b1));
}

// ---------------- fused prep: x -> fp16 AND W -> WT[n][k] fp16 ----------------
// blocks [0, 4096): convert x (one float4 per thread)
// blocks [4096, 4096+16384): transpose-convert one 32x32 tile of W
#define XBLKS (L_SEQ * DDIM / 4 / 256)     // 4096
#define WBLKS ((DDIM / 32) * (KTOT / 32))  // 16384

__global__ void prep_kernel(const float* __restrict__ x, const float* __restrict__ w) {
    __shared__ float tile[32][33];
    int bid = blockIdx.x;
    if (bid < XBLKS) {
        int i = bid * 256 + threadIdx.x;
        float4 v = reinterpret_cast<const float4*>(x)[i];
        __half2* hp = reinterpret_cast<__half2*>(g_x);
        hp[2 * i]     = __halves2half2(__float2half(v.x), __float2half(v.y));
        hp[2 * i + 1] = __halves2half2(__float2half(v.z), __float2half(v.w));
    } else {
        int wb = bid - XBLKS;
        int nt = (wb & 63) * 32;           // DDIM/32 = 64
        int kt = (wb >> 6) * 32;
        int tx = threadIdx.x & 31, ty = threadIdx.x >> 5;
        #pragma unroll
        for (int r = ty; r < 32; r += 8)
            tile[r][tx] = w[(size_t)(kt + r) * DDIM + nt + tx];
        __syncthreads();
        #pragma unroll
        for (int r = ty; r < 32; r += 8) {
            float v = tile[tx][r];         // w[kt+tx][nt+r]
            g_wt[(size_t)(nt + r) * KTOT + kt + tx] = __float2half(v);
        }
    }
}

// ---------------- GEMM tile loader (2 tiles x 1024 chunks) ----------------
__device__ __forceinline__ void load_stage(uint32_t sbase, int stage, int kt,
                                           int bm, int bn, int tid) {
    const int w = kt >> 5;                    // conv tap (32 tiles of 64 per tap)
    const int ibase = (kt & 31) * BK;
    const int kcol = kt * BK;
    const uint32_t st = sbase + stage * STAGE_BYTES;
    #pragma unroll
    for (int it = 0; it < 8; it++) {
        int i = tid + it * 256;
        int tile = i >> 10;                   // 0: A, 1: B
        int idx = i & 1023;
        int r = idx >> 3;                     // 0..127
        int q = idx & 7;                      // 16B chunk in row
        uint32_t dst = st + tile * TILE_BYTES + r * 128 + ((q ^ (r & 7)) << 4);
        if (tile == 0) {
            int xr = bm + r + w - 1;
            int ok = (xr >= 0 && xr < L_SEQ) ? 16 : 0;
            int xc = xr < 0 ? 0 : (xr >= L_SEQ ? L_SEQ - 1 : xr);
            const __half* src = g_x + (size_t)xc * DDIM + ibase + q * 8;
            cp_async_16(dst, src, ok);
        } else {
            const __half* src = g_wt + (size_t)(bn + r) * KTOT + kcol + q * 8;
            cp_async_16(dst, src, 16);
        }
    }
}

// ---------------- GEMM ----------------
__global__ __launch_bounds__(256, 2) void mamba_gemm_mma(
    const float* __restrict__ conv_b, const float* __restrict__ D_param,
    float* __restrict__ out)
{
    extern __shared__ __align__(128) char smem[];
    const uint32_t sbase = smem_u32(smem);
    const int tid  = threadIdx.x;
    const int lane = tid & 31;
    const int wid  = tid >> 5;
    const int wm   = wid & 3;                  // 4 warps along M (32 rows each)
    const int wn   = wid >> 2;                 // 2 warps along N (64 cols each)
    const int bm = blockIdx.y * BM;
    const int bn = blockIdx.x * BN;

    float acc[2][8][4];
    #pragma unroll
    for (int mi = 0; mi < 2; mi++)
        #pragma unroll
        for (int ni = 0; ni < 8; ni++)
            #pragma unroll
            for (int j = 0; j < 4; j++)
                acc[mi][ni][j] = 0.0f;

    const uint32_t a_row   = wm * 32 + (lane & 15);
    const uint32_t a_chunk = (lane >> 4);          // + ks*2
    const uint32_t b_row   = wn * 64 + (lane & 7) + ((lane >> 4) << 3);
    const uint32_t b_chunk = ((lane >> 3) & 1);    // + ks*2

    // prologue: stages 0,1
    load_stage(sbase, 0, 0, bm, bn, tid); CP_COMMIT();
    load_stage(sbase, 1, 1, bm, bn, tid); CP_COMMIT();

    for (int kt = 0; kt < NKT; kt++) {
        // stage kt must be complete; this barrier also makes it safe to
        // overwrite stage (kt+2)%3 == (kt-1)%3 (all reads of it finished
        // in iteration kt-1, strictly before this rendezvous).
        if (kt < NKT - 1) { CP_WAIT1(); } else { CP_WAIT0(); }
        __syncthreads();

        if (kt + 2 < NKT) {
            load_stage(sbase, (kt + 2) % STAGES, kt + 2, bm, bn, tid);
            CP_COMMIT();
        }

        const uint32_t st = sbase + (kt % STAGES) * STAGE_BYTES;
        #pragma unroll
        for (int ks = 0; ks < 4; ks++) {
            uint32_t aa[2][4];
            uint32_t bb[4][4];
            #pragma unroll
            for (int mi = 0; mi < 2; mi++) {
                uint32_t row = a_row + mi * 16;
                uint32_t ar = st + row * 128 + (((ks * 2 + a_chunk) ^ (row & 7)) << 4);
                ldm_x4(aa[mi], ar + A_OFF);
            }
            #pragma unroll
            for (int np = 0; np < 4; np++) {
                uint32_t row = b_row + np * 16;
                uint32_t br = st + row * 128 + (((ks * 2 + b_chunk) ^ (row & 7)) << 4);
                ldm_x4(bb[np], br + B_OFF);
            }
            #pragma unroll
            for (int mi = 0; mi < 2; mi++)
                #pragma unroll
                for (int ni = 0; ni < 8; ni++) {
                    uint32_t b0 = bb[ni >> 1][(ni & 1) * 2];
                    uint32_t b1 = bb[ni >> 1][(ni & 1) * 2 + 1];
                    mma16816(acc[mi][ni], aa[mi], b0, b1);
                }
        }
        // no trailing __syncthreads needed (see comment at top of loop)
    }

    // epilogue: (acc + conv_b[n]) * D_param[n]
    #pragma unroll
    for (int ni = 0; ni < 8; ni++) {
        int c = bn + wn * 64 + ni * 8 + (lane & 3) * 2;
        float2 cb = *reinterpret_cast<const float2*>(conv_b + c);
        float2 dp = *reinterpret_cast<const float2*>(D_param + c);
        #pragma unroll
        for (int mi = 0; mi < 2; mi++) {
            int r0 = bm + wm * 32 + mi * 16 + (lane >> 2);
            float2 o0, o1;
            o0.x = (acc[mi][ni][0] + cb.x) * dp.x;
            o0.y = (acc[mi][ni][1] + cb.y) * dp.y;
            o1.x = (acc[mi][ni][2] + cb.x) * dp.x;
            o1.y = (acc[mi][ni][3] + cb.y) * dp.y;
            *reinterpret_cast<float2*>(out + (size_t)r0 * DDIM + c) = o0;
            *reinterpret_cast<float2*>(out + (size_t)(r0 + 8) * DDIM + c) = o1;
        }
    }
}

// ---------------- launch ----------------
extern "C" void kernel_launch(void* const* d_in, const int* in_sizes, int n_in,
                              void* d_out, int out_size) {
    const float* x       = (const float*)d_in[0];
    const float* conv_k  = (const float*)d_in[3];
    const float* conv_b  = (const float*)d_in[4];
    const float* D_param = (const float*)d_in[6];
    float* out = (float*)d_out;

    prep_kernel<<<XBLKS + WBLKS, 256>>>(x, conv_k);

    cudaFuncSetAttribute(mamba_gemm_mma, cudaFuncAttributeMaxDynamicSharedMemorySize, SMEM_TOTAL);
    mamba_gemm_mma<<<dim3(DDIM / BN, L_SEQ / BM), 256, SMEM_TOTAL>>>(conv_b, D_param, out);
}